// round 5
// baseline (speedup 1.0000x reference)
#include <cuda_runtime.h>
#include <cuda_bf16.h>

// Problem constants
#define BB 65536
#define DD 256
#define KK 32
#define TM 64          // rows per block in main kernel
#define NBLK (BB / TM) // 1024
#define BD (BB * DD)

// Intermediates (no cudaMalloc allowed)
__device__ float g_uhat[KK * DD];
__device__ float g_A[KK * KK];

// ---------- f32x2 helpers (Blackwell packed fp32) ----------
__device__ __forceinline__ unsigned long long ffma2(unsigned long long a,
                                                    unsigned long long b,
                                                    unsigned long long c) {
    unsigned long long d;
    asm("fma.rn.f32x2 %0, %1, %2, %3;" : "=l"(d) : "l"(a), "l"(b), "l"(c));
    return d;
}
__device__ __forceinline__ unsigned long long packf2(float x, float y) {
    unsigned long long r;
    asm("mov.b64 %0, {%1, %2};" : "=l"(r) : "f"(x), "f"(y));
    return r;
}

// ---------- Setup kernel 1: u_hat ----------
__global__ void k_uhat(const float* __restrict__ u, const float* __restrict__ w) {
    __shared__ float red[16];
    __shared__ float s_alpha;
    int k = blockIdx.x, t = threadIdx.x;
    float wk = w[k * DD + t];
    float uk = u[k * DD + t];
    float p = wk * uk;
    float q = wk * wk;
    #pragma unroll
    for (int o = 16; o; o >>= 1) {
        p += __shfl_xor_sync(0xffffffffu, p, o);
        q += __shfl_xor_sync(0xffffffffu, q, o);
    }
    if ((t & 31) == 0) { red[(t >> 5) * 2] = p; red[(t >> 5) * 2 + 1] = q; }
    __syncthreads();
    if (t == 0) {
        float wu = 0.f, ww = 0.f;
        #pragma unroll
        for (int i = 0; i < 8; ++i) { wu += red[2 * i]; ww += red[2 * i + 1]; }
        float sp = fmaxf(wu, 0.f) + log1pf(expf(-fabsf(wu)));  // softplus(wu)
        s_alpha = (sp - 1.0f - wu) / ww;
    }
    __syncthreads();
    g_uhat[k * DD + t] = fmaf(s_alpha, wk, uk);
}

// ---------- Setup kernel 2: A[k][j] = w_k . uhat_j ----------
__global__ void k_A(const float* __restrict__ w) {
    __shared__ float ws[DD];
    int k = blockIdx.x, t = threadIdx.x;
    ws[t] = w[k * DD + t];
    __syncthreads();
    int j = t >> 3, s = t & 7;
    const float* up = g_uhat + j * DD + s * 32;
    const float* wp = ws + s * 32;
    float p = 0.f;
    #pragma unroll
    for (int i = 0; i < 32; ++i) p = fmaf(wp[i], up[i], p);
    p += __shfl_xor_sync(0xffffffffu, p, 1);
    p += __shfl_xor_sync(0xffffffffu, p, 2);
    p += __shfl_xor_sync(0xffffffffu, p, 4);
    if (s == 0) g_A[k * KK + j] = p;
}

// ---------- Main fused kernel ----------
// Smem layout (float offsets):
//  XS : 0      .. 16448   X tile, stride 257 (conflict-free scalar col reads)
//  WT : 16448  .. +9216   W transposed [d][k], stride 36 (16B-aligned vec loads)
//  PC : 25664  .. +17408  per-warp partial C, [w][r(stride34)][k]  (aliased by UH)
//  UH : 25664  .. +8192   uhat [k][d] (loaded after PC is consumed)
//  CS : 43072  .. +2112   C tile [r(stride33)][k]
//  TS : 45184  .. +2304   T tile [r(stride36)][k]
//  AS : 47488  .. +1024   A matrix
// total 48512 floats = 194048 bytes
#define OFF_XS 0
#define OFF_WT 16448
#define OFF_PC 25664
#define OFF_UH 25664
#define OFF_CS 43072
#define OFF_TS 45184
#define OFF_AS 47488
#define SMEM_FLOATS 48512

__global__ __launch_bounds__(256, 1)
void nf_main(const float* __restrict__ X, const float* __restrict__ w,
             const float* __restrict__ bvec, float* __restrict__ out) {
    extern __shared__ float sm[];
    float* XS = sm + OFF_XS;
    float* WT = sm + OFF_WT;
    float* PC = sm + OFF_PC;
    float* UH = sm + OFF_UH;
    float* CS = sm + OFF_CS;
    float* TS = sm + OFF_TS;
    float* AS = sm + OFF_AS;

    const int t = threadIdx.x;
    const int r0 = blockIdx.x * TM;

    // ---- Prologue: stage X tile (pad 257), W transposed (pad 36), A ----
    {
        const float* Xb = X + (size_t)r0 * DD;
        #pragma unroll 4
        for (int n = 0; n < TM; ++n) XS[n * 257 + t] = Xb[n * DD + t];
        for (int i = t; i < KK * DD; i += 256) {
            int k = i >> 8, d = i & 255;
            WT[d * 36 + k] = w[i];
        }
        for (int i = t; i < KK * KK; i += 256) AS[i] = g_A[i];
    }
    __syncthreads();

    // ---- Phase 1: partial C = X . W^T, warp wp owns d-range [32*wp, 32*wp+32)
    //      lane l owns rows l and l+32; k packed in f32x2 pairs ----
    {
        const int wp = t >> 5, l = t & 31;
        unsigned long long cc[2][16];
        #pragma unroll
        for (int i = 0; i < 16; ++i) { cc[0][i] = 0ull; cc[1][i] = 0ull; }
        const int dbase = wp * 32;
        #pragma unroll 4
        for (int dd = 0; dd < 32; ++dd) {
            const int d = dbase + dd;
            float x0 = XS[l * 257 + d];
            float x1 = XS[(l + 32) * 257 + d];
            unsigned long long xx0 = packf2(x0, x0);
            unsigned long long xx1 = packf2(x1, x1);
            const ulonglong2* wrow = (const ulonglong2*)&WT[d * 36];
            #pragma unroll
            for (int q = 0; q < 8; ++q) {
                ulonglong2 wv = wrow[q];
                cc[0][2 * q]     = ffma2(xx0, wv.x, cc[0][2 * q]);
                cc[0][2 * q + 1] = ffma2(xx0, wv.y, cc[0][2 * q + 1]);
                cc[1][2 * q]     = ffma2(xx1, wv.x, cc[1][2 * q]);
                cc[1][2 * q + 1] = ffma2(xx1, wv.y, cc[1][2 * q + 1]);
            }
        }
        #pragma unroll
        for (int kp = 0; kp < 16; ++kp) {
            *(unsigned long long*)&PC[wp * 2176 + l * 34 + 2 * kp]        = cc[0][kp];
            *(unsigned long long*)&PC[wp * 2176 + (l + 32) * 34 + 2 * kp] = cc[1][kp];
        }
    }
    __syncthreads();

    // ---- Reduce 8 warp-partials -> CS ----
    {
        const int rr = t >> 2, kb = (t & 3) * 8;
        #pragma unroll
        for (int j = 0; j < 8; ++j) {
            int k = kb + j;
            float s = 0.f;
            #pragma unroll
            for (int ww = 0; ww < 8; ++ww) s += PC[ww * 2176 + rr * 34 + k];
            CS[rr * 33 + k] = s;
        }
    }
    __syncthreads();

    // ---- Phase 2: triangular recurrence (warps 0-1) + UH stage (warps 2-7) ----
    if (t < TM) {
        const int r = t;
        float tl[KK];
        #pragma unroll
        for (int k = 0; k < KK; ++k) {
            float lin = CS[r * 33 + k] + __ldg(&bvec[k]);
            #pragma unroll
            for (int j = 0; j < k; ++j) lin = fmaf(AS[k * KK + j], tl[j], lin);
            float tk = tanhf(lin);
            tl[k] = tk;
            TS[r * 36 + k] = tk;
            float akk = AS[k * 33];  // A[k][k]
            float ldv = logf(fabsf(fmaf(1.0f - tk * tk, akk, 1.0f)) + 1e-8f);
            out[BD + k * BB + r0 + r] = ldv;   // coalesced per k across warp
        }
    } else {
        for (int i = t - TM; i < KK * DD; i += 256 - TM) UH[i] = g_uhat[i];
    }
    __syncthreads();

    // ---- Phase 3: Z = X + T . Uhat ----
    {
        const int tx = t & 31, ty = t >> 5;
        const int c0 = tx * 4, c1 = 128 + tx * 4;
        ulonglong2 a0[8], a1[8];
        #pragma unroll
        for (int i = 0; i < 8; ++i) {
            const float* xr = X + (size_t)(r0 + ty * 8 + i) * DD;
            a0[i] = *(const ulonglong2*)(xr + c0);
            a1[i] = *(const ulonglong2*)(xr + c1);
        }
        #pragma unroll
        for (int kc = 0; kc < 4; ++kc) {
            const int k0 = kc * 8;
            ulonglong2 u0[8], u1[8];
            #pragma unroll
            for (int kk = 0; kk < 8; ++kk) {
                u0[kk] = *(const ulonglong2*)&UH[(k0 + kk) * DD + c0];
                u1[kk] = *(const ulonglong2*)&UH[(k0 + kk) * DD + c1];
            }
            #pragma unroll
            for (int i = 0; i < 8; ++i) {
                const int r = ty * 8 + i;
                float4 ta = *(const float4*)&TS[r * 36 + k0];
                float4 tb = *(const float4*)&TS[r * 36 + k0 + 4];
                float tv[8] = {ta.x, ta.y, ta.z, ta.w, tb.x, tb.y, tb.z, tb.w};
                #pragma unroll
                for (int kk = 0; kk < 8; ++kk) {
                    unsigned long long tt = packf2(tv[kk], tv[kk]);
                    a0[i].x = ffma2(tt, u0[kk].x, a0[i].x);
                    a0[i].y = ffma2(tt, u0[kk].y, a0[i].y);
                    a1[i].x = ffma2(tt, u1[kk].x, a1[i].x);
                    a1[i].y = ffma2(tt, u1[kk].y, a1[i].y);
                }
            }
        }
        #pragma unroll
        for (int i = 0; i < 8; ++i) {
            float* zr = out + (size_t)(r0 + ty * 8 + i) * DD;
            *(ulonglong2*)(zr + c0) = a0[i];
            *(ulonglong2*)(zr + c1) = a1[i];
        }
    }
}

extern "C" void kernel_launch(void* const* d_in, const int* in_sizes, int n_in,
                              void* d_out, int out_size) {
    const float* X = (const float*)d_in[0];
    // d_in[1] = h (unused by planar flow math)
    const float* u = (const float*)d_in[2];
    const float* w = (const float*)d_in[3];
    const float* b = (const float*)d_in[4];
    float* out = (float*)d_out;

    k_uhat<<<KK, 256>>>(u, w);
    k_A<<<KK, 256>>>(w);

    cudaFuncSetAttribute(nf_main, cudaFuncAttributeMaxDynamicSharedMemorySize,
                         SMEM_FLOATS * (int)sizeof(float));
    nf_main<<<NBLK, 256, SMEM_FLOATS * sizeof(float)>>>(X, w, b, out);
}